// round 10
// baseline (speedup 1.0000x reference)
#include <cuda_runtime.h>
#include <math.h>

#define SEQ   2048
#define BATCH 64
#define DIN   512
#define DH    512

typedef unsigned long long u64;

// ---------------- f32x2 packed helpers ----------------
__device__ __forceinline__ u64 dupf(float x) {
    u64 d; asm("mov.b64 %0, {%1, %1};" : "=l"(d) : "f"(x)); return d;
}
__device__ __forceinline__ void fma2(u64& acc, u64 a, u64 b) {
    asm("fma.rn.f32x2 %0, %1, %2, %0;" : "+l"(acc) : "l"(a), "l"(b));
}
__device__ __forceinline__ float2 unpack2(u64 v) {
    float lo, hi;
    asm("mov.b64 {%0, %1}, %2;" : "=f"(lo), "=f"(hi) : "l"(v));
    return make_float2(lo, hi);
}
__device__ __forceinline__ u64 packf2(float lo, float hi) {
    u64 d; asm("mov.b64 %0, {%1, %2};" : "=l"(d) : "f"(lo), "f"(hi)); return d;
}

// ---------------- cluster helpers ----------------
__device__ __forceinline__ unsigned smem_u32(const void* p) {
    unsigned r;
    asm("{ .reg .u64 t; cvta.to.shared.u64 t, %1; cvt.u32.u64 %0, t; }"
        : "=r"(r) : "l"(p));
    return r;
}
__device__ __forceinline__ unsigned cluster_rank() {
    unsigned r; asm("mov.u32 %0, %%cluster_ctarank;" : "=r"(r)); return r;
}
__device__ __forceinline__ unsigned mapa_u32(unsigned addr, unsigned rank) {
    unsigned r;
    asm("mapa.shared::cluster.u32 %0, %1, %2;" : "=r"(r) : "r"(addr), "r"(rank));
    return r;
}
__device__ __forceinline__ void st_cluster_u64(unsigned addr, u64 v) {
    asm volatile("st.shared::cluster.b64 [%0], %1;" :: "r"(addr), "l"(v) : "memory");
}
__device__ __forceinline__ void cluster_sync_hw() {
    asm volatile("barrier.cluster.arrive.aligned;" ::: "memory");
    asm volatile("barrier.cluster.wait.aligned;" ::: "memory");
}

// ---------------- XLA fast tanh: clamp 7.99881172180175781, passthrough ----------------
__device__ __forceinline__ float xla_tanh(float x) {
    const float kClamp = 7.99881172180175781f;
    float ax = fabsf(x);
    float xc = fminf(fmaxf(x, -kClamp), kClamp);
    float x2 = xc * xc;
    float p = __fmaf_rn(x2, -2.76076847742355e-16f, 2.00018790482477e-13f);
    p = __fmaf_rn(x2, p, -8.60467152213735e-11f);
    p = __fmaf_rn(x2, p, 5.12229709037114e-08f);
    p = __fmaf_rn(x2, p, 1.48572235717979e-05f);
    p = __fmaf_rn(x2, p, 6.37261928875436e-04f);
    p = __fmaf_rn(x2, p, 4.89352455891786e-03f);
    p = xc * p;
    float q = __fmaf_rn(x2, 1.19825839466702e-06f, 1.18534705686654e-04f);
    q = __fmaf_rn(x2, q, 2.26843463243900e-03f);
    q = __fmaf_rn(x2, q, 4.89352518554385e-03f);
    float r = __fdiv_rn(p, q);
    return (ax < 0.0004f) ? x : r;
}

// ---------------- Kernel 1: xi = x @ W_i2h^T + b_i2h (f32x2 packed) ----------------
#define BM 64
#define BN 64
#define BK 16

__global__ void __launch_bounds__(256) i2h_gemm_kernel(
    const float* __restrict__ A, const float* __restrict__ Bw,
    const float* __restrict__ bias, float* __restrict__ C)
{
    __shared__ float As[BK][BM + 4];
    __shared__ float Bs[BK][BN + 4];
    const int bm = blockIdx.x, bn = blockIdx.y, tid = threadIdx.x;
    const int tm = (tid / 16) * 4, tn = (tid % 16) * 4;
    const int lr = tid / 4, lk = (tid % 4) * 4;
    const float* Aptr = A + ((size_t)bm * BM + lr) * DIN + lk;
    const float* Bptr = Bw + ((size_t)bn * BN + lr) * DIN + lk;

    u64 acc2[4][2];
    #pragma unroll
    for (int i = 0; i < 4; i++) { acc2[i][0] = 0ull; acc2[i][1] = 0ull; }

    for (int k0 = 0; k0 < DIN; k0 += BK) {
        float4 av = *(const float4*)(Aptr + k0);
        float4 bv = *(const float4*)(Bptr + k0);
        As[lk + 0][lr] = av.x; As[lk + 1][lr] = av.y;
        As[lk + 2][lr] = av.z; As[lk + 3][lr] = av.w;
        Bs[lk + 0][lr] = bv.x; Bs[lk + 1][lr] = bv.y;
        Bs[lk + 2][lr] = bv.z; Bs[lk + 3][lr] = bv.w;
        __syncthreads();
        #pragma unroll
        for (int k = 0; k < BK; k++) {
            float4 a4 = *(const float4*)&As[k][tm];
            u64 b01 = *(const u64*)&Bs[k][tn];
            u64 b23 = *(const u64*)&Bs[k][tn + 2];
            float am[4] = {a4.x, a4.y, a4.z, a4.w};
            #pragma unroll
            for (int i = 0; i < 4; i++) {
                u64 ad = dupf(am[i]);
                fma2(acc2[i][0], ad, b01);
                fma2(acc2[i][1], ad, b23);
            }
        }
        __syncthreads();
    }

    const float b0 = bias[bn * BN + tn + 0];
    const float b1 = bias[bn * BN + tn + 1];
    const float b2 = bias[bn * BN + tn + 2];
    const float b3 = bias[bn * BN + tn + 3];
    #pragma unroll
    for (int i = 0; i < 4; i++) {
        float2 p0 = unpack2(acc2[i][0]);
        float2 p1 = unpack2(acc2[i][1]);
        float4 o;
        o.x = p0.x + b0;
        o.y = p0.y + b1;
        o.z = p1.x + b2;
        o.w = p1.y + b3;
        *(float4*)&C[((size_t)bm * BM + tm + i) * DH + bn * BN + tn] = o;
    }
}

// ---------------- Kernel 2: persistent scan, 16-CTA clusters + DSMEM push ----------------
// 128 CTAs = 8 clusters (batch groups of 8 rows) x 16 CTAs (col groups of 32).
// Per thread: col-pair P = 4*warp + (lane&3), row r = lane>>2; one ascending-k
// f32x2 chain -> (xi+dot)+b -> xla_tanh. h exchanged via st.shared::cluster
// into every cluster CTA's double-buffered h smem; one barrier.cluster per step.
#define WPST 257            // W pair stride in float4
#define HST4 129            // h row stride in float4
#define HBUF4 (8 * HST4)    // one h buffer = 1032 float4
#define SMEM_F4 (16 * WPST + 2 * HBUF4)   // 4112 + 2064 = 6176 float4 = 98816 B

__global__ void __launch_bounds__(128, 1) __cluster_dims__(16, 1, 1)
rnn_scan_kernel(
    const float* __restrict__ h0, const float* __restrict__ W_h2h,
    const float* __restrict__ b_h2h, float* __restrict__ out,
    float* __restrict__ h_last)
{
    extern __shared__ float4 sm4[];
    float4* W4s = sm4;                    // [16][WPST]
    float4* hb  = sm4 + 16 * WPST;        // [2][8][HST4]

    const unsigned rank = cluster_rank(); // == col group cg
    const int cg = (int)rank;
    const int bg = blockIdx.x >> 4;
    const int c0 = cg * 32;
    const int b0 = bg * 8;
    const int tid = threadIdx.x;
    const int lane = tid & 31;
    const int warp = tid >> 5;
    const int P = warp * 4 + (lane & 3);     // col-pair 0..15
    const int r = lane >> 2;                 // row 0..7
    const int c = c0 + 2 * P;

    // peer smem base addresses (cluster window)
    unsigned my_base = smem_u32(sm4);
    unsigned peer_base[16];
    #pragma unroll
    for (int p = 0; p < 16; p++) peer_base[p] = mapa_u32(my_base, (unsigned)p);

    // byte offset of my h slot within a buffer-parity:
    // hb starts at 16*WPST float4; slot = [r][col = rank*32 + 2P]
    const unsigned hslot = (unsigned)(16 * WPST * 16)     // hb byte offset
                         + (unsigned)(r * HST4 * 16)      // row
                         + (unsigned)(rank * 128 + P * 8);// col pair
    const unsigned hbuf_bytes = (unsigned)(HBUF4 * 16);

    // stage W interleaved: W4s[P][k2] = (W[c][2k2], W[c+1][2k2], W[c][2k2+1], W[c+1][2k2+1])
    for (int idx = tid; idx < 16 * 256; idx += 128) {
        int p = idx >> 8, k2 = idx & 255;
        float2 a = *(const float2*)(W_h2h + (size_t)(c0 + 2 * p) * DH + 2 * k2);
        float2 b = *(const float2*)(W_h2h + (size_t)(c0 + 2 * p + 1) * DH + 2 * k2);
        W4s[p * WPST + k2] = make_float4(a.x, b.x, a.y, b.y);
    }

    // preload h0 rows b0..b0+7 into buffer parity 1 (read parity of t=0)
    {
        const int lr = tid >> 4;
        const int kc = tid & 15;
        const float4* hsrc = (const float4*)(h0 + (size_t)(b0 + lr) * DH);
        float4* hdst = hb + HBUF4 + lr * HST4;
        #pragma unroll
        for (int j = 0; j < 8; j++)
            hdst[kc + 16 * j] = hsrc[kc + 16 * j];
    }

    const float bias0 = b_h2h[c];
    const float bias1 = b_h2h[c + 1];
    const ulonglong2* Wp = (const ulonglong2*)(W4s + (size_t)P * WPST);
    const size_t rowoff = (size_t)(b0 + r) * DH + c;   // + t*BATCH*DH

    // prefetch xi(0)
    float2 xi = *(const float2*)(out + rowoff);

    __syncthreads();
    cluster_sync_hw();   // W + h0 staged in every cluster CTA

    for (int t = 0; t < SEQ; t++) {
        const int rp = 1 ^ (t & 1);   // h(t-1) buffer parity
        const int wp = t & 1;         // h(t) buffer parity
        const float4* Hp = hb + rp * HBUF4 + r * HST4;

        // two ascending-k chains packed in one fma.rn.f32x2 stream
        u64 acc = 0ull;
        #pragma unroll 16
        for (int k4 = 0; k4 < 128; k4++) {
            float4 hv = Hp[k4];
            ulonglong2 w0 = Wp[2 * k4];
            ulonglong2 w1 = Wp[2 * k4 + 1];
            fma2(acc, dupf(hv.x), w0.x);
            fma2(acc, dupf(hv.y), w0.y);
            fma2(acc, dupf(hv.z), w1.x);
            fma2(acc, dupf(hv.w), w1.y);
        }
        float2 d = unpack2(acc);
        float v0 = xla_tanh((xi.x + d.x) + bias0);
        float v1 = xla_tanh((xi.y + d.y) + bias1);

        // fire-and-forget global output (nobody reads it back on the hot path)
        *(float2*)(out + (size_t)t * BATCH * DH + rowoff) = make_float2(v0, v1);

        if (t == SEQ - 1) {
            if (h_last) *(float2*)(h_last + rowoff) = make_float2(v0, v1);
        } else {
            // push my two h values into all 16 cluster CTAs' h buffers
            u64 hv64 = packf2(v0, v1);
            const unsigned off = hslot + (unsigned)wp * hbuf_bytes;
            #pragma unroll
            for (int p = 0; p < 16; p++)
                st_cluster_u64(peer_base[p] + off, hv64);

            // prefetch xi(t+1) (out[t+1] still holds xi; only this thread
            // ever writes this address, at step t+1)
            xi = *(const float2*)(out + (size_t)(t + 1) * BATCH * DH + rowoff);

            // release my pushes / acquire peers' pushes
            cluster_sync_hw();
        }
    }
}

// ---------------- launch (single stream, graph-capture-safe) ----------------
extern "C" void kernel_launch(void* const* d_in, const int* in_sizes, int n_in,
                              void* d_out, int out_size) {
    const float* x     = (const float*)d_in[0];
    const float* h0    = (const float*)d_in[1];
    const float* W_i2h = (const float*)d_in[2];
    const float* b_i2h = (const float*)d_in[3];
    const float* W_h2h = (const float*)d_in[4];
    const float* b_h2h = (const float*)d_in[5];
    float* out = (float*)d_out;

    float* h_last = nullptr;
    if ((long long)out_size >= (long long)(SEQ + 1) * BATCH * DH)
        h_last = out + (size_t)SEQ * BATCH * DH;

    dim3 g1(SEQ * BATCH / BM, DH / BN);
    i2h_gemm_kernel<<<g1, 256>>>(x, W_i2h, b_i2h, out);

    const int smem = SMEM_F4 * 16;
    cudaFuncSetAttribute(rnn_scan_kernel,
                         cudaFuncAttributeMaxDynamicSharedMemorySize, smem);
    cudaFuncSetAttribute(rnn_scan_kernel,
                         cudaFuncAttributeNonPortableClusterSizeAllowed, 1);
    rnn_scan_kernel<<<128, 128, smem>>>(h0, W_h2h, b_h2h, out, h_last);
}

// round 11
// speedup vs baseline: 1.0557x; 1.0557x over previous
#include <cuda_runtime.h>
#include <math.h>

#define SEQ   2048
#define BATCH 64
#define DIN   512
#define DH    512

typedef unsigned long long u64;

// ---------------- f32x2 packed helpers ----------------
__device__ __forceinline__ u64 dupf(float x) {
    u64 d; asm("mov.b64 %0, {%1, %1};" : "=l"(d) : "f"(x)); return d;
}
__device__ __forceinline__ void fma2(u64& acc, u64 a, u64 b) {
    asm("fma.rn.f32x2 %0, %1, %2, %0;" : "+l"(acc) : "l"(a), "l"(b));
}
__device__ __forceinline__ float2 unpack2(u64 v) {
    float lo, hi;
    asm("mov.b64 {%0, %1}, %2;" : "=f"(lo), "=f"(hi) : "l"(v));
    return make_float2(lo, hi);
}

// ---------------- XLA fast tanh: clamp 7.99881172180175781, passthrough ----------------
__device__ __forceinline__ float xla_tanh(float x) {
    const float kClamp = 7.99881172180175781f;
    float ax = fabsf(x);
    float xc = fminf(fmaxf(x, -kClamp), kClamp);
    float x2 = xc * xc;
    float p = __fmaf_rn(x2, -2.76076847742355e-16f, 2.00018790482477e-13f);
    p = __fmaf_rn(x2, p, -8.60467152213735e-11f);
    p = __fmaf_rn(x2, p, 5.12229709037114e-08f);
    p = __fmaf_rn(x2, p, 1.48572235717979e-05f);
    p = __fmaf_rn(x2, p, 6.37261928875436e-04f);
    p = __fmaf_rn(x2, p, 4.89352455891786e-03f);
    p = xc * p;
    float q = __fmaf_rn(x2, 1.19825839466702e-06f, 1.18534705686654e-04f);
    q = __fmaf_rn(x2, q, 2.26843463243900e-03f);
    q = __fmaf_rn(x2, q, 4.89352518554385e-03f);
    float r = __fdiv_rn(p, q);
    return (ax < 0.0004f) ? x : r;
}

// ---------------- global state ----------------
// h ring: small, L2-resident, double-buffered. h(t) written to g_ring[t&1].
__device__ float g_ring[2][BATCH][DH];
// flags: g_flag[(bg*8+cg)*32]; monotone within a replay; reset at t==SEQ-1.
__device__ volatile unsigned g_flag[8 * 8 * 32];

// ---------------- Kernel 1: xi = x @ W_i2h^T + b_i2h (f32x2 packed) ----------------
#define BM 64
#define BN 64
#define BK 16

__global__ void __launch_bounds__(256) i2h_gemm_kernel(
    const float* __restrict__ A, const float* __restrict__ Bw,
    const float* __restrict__ bias, float* __restrict__ C)
{
    __shared__ float As[BK][BM + 4];
    __shared__ float Bs[BK][BN + 4];
    const int bm = blockIdx.x, bn = blockIdx.y, tid = threadIdx.x;
    const int tm = (tid / 16) * 4, tn = (tid % 16) * 4;
    const int lr = tid / 4, lk = (tid % 4) * 4;
    const float* Aptr = A + ((size_t)bm * BM + lr) * DIN + lk;
    const float* Bptr = Bw + ((size_t)bn * BN + lr) * DIN + lk;

    u64 acc2[4][2];
    #pragma unroll
    for (int i = 0; i < 4; i++) { acc2[i][0] = 0ull; acc2[i][1] = 0ull; }

    for (int k0 = 0; k0 < DIN; k0 += BK) {
        float4 av = *(const float4*)(Aptr + k0);
        float4 bv = *(const float4*)(Bptr + k0);
        As[lk + 0][lr] = av.x; As[lk + 1][lr] = av.y;
        As[lk + 2][lr] = av.z; As[lk + 3][lr] = av.w;
        Bs[lk + 0][lr] = bv.x; Bs[lk + 1][lr] = bv.y;
        Bs[lk + 2][lr] = bv.z; Bs[lk + 3][lr] = bv.w;
        __syncthreads();
        #pragma unroll
        for (int k = 0; k < BK; k++) {
            float4 a4 = *(const float4*)&As[k][tm];
            u64 b01 = *(const u64*)&Bs[k][tn];
            u64 b23 = *(const u64*)&Bs[k][tn + 2];
            float am[4] = {a4.x, a4.y, a4.z, a4.w};
            #pragma unroll
            for (int i = 0; i < 4; i++) {
                u64 ad = dupf(am[i]);
                fma2(acc2[i][0], ad, b01);
                fma2(acc2[i][1], ad, b23);
            }
        }
        __syncthreads();
    }

    const float b0 = bias[bn * BN + tn + 0];
    const float b1 = bias[bn * BN + tn + 1];
    const float b2 = bias[bn * BN + tn + 2];
    const float b3 = bias[bn * BN + tn + 3];
    #pragma unroll
    for (int i = 0; i < 4; i++) {
        float2 p0 = unpack2(acc2[i][0]);
        float2 p1 = unpack2(acc2[i][1]);
        float4 o;
        o.x = p0.x + b0;
        o.y = p0.y + b1;
        o.z = p1.x + b2;
        o.w = p1.y + b3;
        *(float4*)&C[((size_t)bm * BM + tm + i) * DH + bn * BN + tn] = o;
    }
}

// ---------------- Kernel 2: persistent scan ----------------
// 64 CTAs = bg(8 x 8 rows) x cg(8 x 64 cols). 128 threads = 4 warps.
// Thread: col-pair P = 8*warp + (lane&7), rows r0 = 2*(lane>>3), r1 = r0+1.
// Two independent ascending-k f32x2 chains per thread (share the W stream).
// h staged in smem PRE-DUPLICATED as (h,h) u64 pairs -> no dup MOVs in loop.
#define WPST 257              // W pair stride in float4 (16B units)
#define HDST 516              // h-dup row stride in u64 (stride*8 % 128 == 32)
#define SMEM_BYTES (32 * WPST * 16 + 8 * HDST * 8)   // 131584 + 33024 = 164608

__global__ void __launch_bounds__(128, 1) rnn_scan_kernel(
    const float* __restrict__ h0, const float* __restrict__ W_h2h,
    const float* __restrict__ b_h2h, float* __restrict__ out,
    float* __restrict__ h_last)
{
    extern __shared__ float4 sm4[];
    float4* W4s = sm4;                        // [32][WPST]
    u64* hdup   = (u64*)(sm4 + 32 * WPST);    // [8][HDST]

    const int cg = blockIdx.x & 7;
    const int bg = blockIdx.x >> 3;
    const int c0 = cg * 64;
    const int b0 = bg * 8;
    const int tid = threadIdx.x;
    const int lane = tid & 31;
    const int warp = tid >> 5;
    const int P  = warp * 8 + (lane & 7);     // col-pair 0..31
    const int r0 = 2 * (lane >> 3);           // 0,2,4,6
    const int r1 = r0 + 1;
    const int c  = c0 + 2 * P;

    // stage W interleaved: W4s[P][k2] = (W[c][2k2], W[c+1][2k2], W[c][2k2+1], W[c+1][2k2+1])
    for (int idx = tid; idx < 32 * 256; idx += 128) {
        int p = idx >> 8, k2 = idx & 255;
        float2 a = *(const float2*)(W_h2h + (size_t)(c0 + 2 * p) * DH + 2 * k2);
        float2 b = *(const float2*)(W_h2h + (size_t)(c0 + 2 * p + 1) * DH + 2 * k2);
        W4s[p * WPST + k2] = make_float4(a.x, b.x, a.y, b.y);
    }

    const float bias0 = b_h2h[c];
    const float bias1 = b_h2h[c + 1];
    const ulonglong2* Wp  = (const ulonglong2*)(W4s + (size_t)P * WPST);
    const ulonglong2* H0p = (const ulonglong2*)(hdup + (size_t)r0 * HDST);
    const ulonglong2* H1p = (const ulonglong2*)(hdup + (size_t)r1 * HDST);

    // staging map: thread covers row lr, 8 strided float4 chunks
    const int lr = tid >> 4;
    const int kc = tid & 15;
    u64* hdrow = hdup + lr * HDST;

    const size_t row0off = (size_t)(b0 + r0) * DH + c;   // + t*BATCH*DH
    const size_t row1off = (size_t)(b0 + r1) * DH + c;
    const int flag_base = bg * 8;

    // prefetch xi(0)
    float2 xi0 = *(const float2*)(out + row0off);
    float2 xi1 = *(const float2*)(out + row1off);
    __syncthreads();

    for (int t = 0; t < SEQ; t++) {
        // ---- stage h(t-1) into smem, pre-duplicated ----
        const float4* hsrc = (t == 0)
            ? (const float4*)(h0 + (size_t)(b0 + lr) * DH)
            : (const float4*)(g_ring[1 ^ (t & 1)][b0 + lr]);
        #pragma unroll
        for (int j = 0; j < 8; j++) {
            int k4 = kc + 16 * j;
            float4 v = hsrc[k4];
            ulonglong2 d0, d1;
            d0.x = dupf(v.x); d0.y = dupf(v.y);
            d1.x = dupf(v.z); d1.y = dupf(v.w);
            *(ulonglong2*)(hdrow + 4 * k4)     = d0;
            *(ulonglong2*)(hdrow + 4 * k4 + 2) = d1;
        }
        __syncthreads();

        // ---- two ascending-k chains (share W stream) ----
        u64 acc0 = 0ull, acc1 = 0ull;
        #pragma unroll 16
        for (int k4 = 0; k4 < 128; k4++) {
            ulonglong2 w0 = Wp[2 * k4];
            ulonglong2 w1 = Wp[2 * k4 + 1];
            ulonglong2 hA = H0p[2 * k4];
            ulonglong2 hA2 = H0p[2 * k4 + 1];
            ulonglong2 hB = H1p[2 * k4];
            ulonglong2 hB2 = H1p[2 * k4 + 1];
            fma2(acc0, hA.x,  w0.x);
            fma2(acc0, hA.y,  w0.y);
            fma2(acc0, hA2.x, w1.x);
            fma2(acc0, hA2.y, w1.y);
            fma2(acc1, hB.x,  w0.x);
            fma2(acc1, hB.y,  w0.y);
            fma2(acc1, hB2.x, w1.x);
            fma2(acc1, hB2.y, w1.y);
        }
        float2 d0 = unpack2(acc0);
        float2 d1 = unpack2(acc1);
        float v00 = xla_tanh((xi0.x + d0.x) + bias0);
        float v01 = xla_tanh((xi0.y + d0.y) + bias1);
        float v10 = xla_tanh((xi1.x + d1.x) + bias0);
        float v11 = xla_tanh((xi1.y + d1.y) + bias1);

        // fire-and-forget output
        *(float2*)(out + (size_t)t * BATCH * DH + row0off) = make_float2(v00, v01);
        *(float2*)(out + (size_t)t * BATCH * DH + row1off) = make_float2(v10, v11);

        if (t == SEQ - 1) {
            if (h_last) {
                *(float2*)(h_last + row0off) = make_float2(v00, v01);
                *(float2*)(h_last + row1off) = make_float2(v10, v11);
            }
            __syncthreads();
            if (tid == 0) g_flag[(flag_base + cg) * 32] = 0u;   // replay-clean
        } else {
            // h(t) into the hot L2 ring
            *(float2*)(&g_ring[t & 1][b0 + r0][c]) = make_float2(v00, v01);
            *(float2*)(&g_ring[t & 1][b0 + r1][c]) = make_float2(v10, v11);
            // prefetch xi(t+1) (covered by poll + stage + chain)
            xi0 = *(const float2*)(out + (size_t)(t + 1) * BATCH * DH + row0off);
            xi1 = *(const float2*)(out + (size_t)(t + 1) * BATCH * DH + row1off);
            __threadfence();
            __syncthreads();
            if (tid == 0) g_flag[(flag_base + cg) * 32] = (unsigned)(t + 1);
            if (tid < 8) {
                volatile unsigned* f = &g_flag[(flag_base + tid) * 32];
                while (*f < (unsigned)(t + 1)) { }
            }
            __threadfence();
            __syncthreads();
        }
    }
}

// ---------------- launch (single stream, graph-capture-safe) ----------------
extern "C" void kernel_launch(void* const* d_in, const int* in_sizes, int n_in,
                              void* d_out, int out_size) {
    const float* x     = (const float*)d_in[0];
    const float* h0    = (const float*)d_in[1];
    const float* W_i2h = (const float*)d_in[2];
    const float* b_i2h = (const float*)d_in[3];
    const float* W_h2h = (const float*)d_in[4];
    const float* b_h2h = (const float*)d_in[5];
    float* out = (float*)d_out;

    float* h_last = nullptr;
    if ((long long)out_size >= (long long)(SEQ + 1) * BATCH * DH)
        h_last = out + (size_t)SEQ * BATCH * DH;

    dim3 g1(SEQ * BATCH / BM, DH / BN);
    i2h_gemm_kernel<<<g1, 256>>>(x, W_i2h, b_i2h, out);

    cudaFuncSetAttribute(rnn_scan_kernel,
                         cudaFuncAttributeMaxDynamicSharedMemorySize, SMEM_BYTES);
    rnn_scan_kernel<<<64, 128, SMEM_BYTES>>>(h0, W_h2h, b_h2h, out, h_last);
}

// round 12
// speedup vs baseline: 1.0857x; 1.0284x over previous
#include <cuda_runtime.h>
#include <math.h>

#define SEQ   2048
#define BATCH 64
#define DIN   512
#define DH    512

typedef unsigned long long u64;

// ---------------- f32x2 packed helpers (GEMM only) ----------------
__device__ __forceinline__ u64 dupf(float x) {
    u64 d; asm("mov.b64 %0, {%1, %1};" : "=l"(d) : "f"(x)); return d;
}
__device__ __forceinline__ void fma2(u64& acc, u64 a, u64 b) {
    asm("fma.rn.f32x2 %0, %1, %2, %0;" : "+l"(acc) : "l"(a), "l"(b));
}
__device__ __forceinline__ float2 unpack2(u64 v) {
    float lo, hi;
    asm("mov.b64 {%0, %1}, %2;" : "=f"(lo), "=f"(hi) : "l"(v));
    return make_float2(lo, hi);
}

// ---------------- release/acquire flag ops ----------------
__device__ __forceinline__ void st_release_gpu(unsigned* p, unsigned v) {
    asm volatile("st.global.release.gpu.u32 [%0], %1;" :: "l"(p), "r"(v) : "memory");
}
__device__ __forceinline__ unsigned ld_acquire_gpu(const unsigned* p) {
    unsigned v;
    asm volatile("ld.global.acquire.gpu.u32 %0, [%1];" : "=r"(v) : "l"(p) : "memory");
    return v;
}

// ---------------- XLA fast tanh: clamp 7.99881172180175781, passthrough ----------------
__device__ __forceinline__ float xla_tanh(float x) {
    const float kClamp = 7.99881172180175781f;
    float ax = fabsf(x);
    float xc = fminf(fmaxf(x, -kClamp), kClamp);
    float x2 = xc * xc;
    float p = __fmaf_rn(x2, -2.76076847742355e-16f, 2.00018790482477e-13f);
    p = __fmaf_rn(x2, p, -8.60467152213735e-11f);
    p = __fmaf_rn(x2, p, 5.12229709037114e-08f);
    p = __fmaf_rn(x2, p, 1.48572235717979e-05f);
    p = __fmaf_rn(x2, p, 6.37261928875436e-04f);
    p = __fmaf_rn(x2, p, 4.89352455891786e-03f);
    p = xc * p;
    float q = __fmaf_rn(x2, 1.19825839466702e-06f, 1.18534705686654e-04f);
    q = __fmaf_rn(x2, q, 2.26843463243900e-03f);
    q = __fmaf_rn(x2, q, 4.89352518554385e-03f);
    float r = __fdiv_rn(p, q);
    return (ax < 0.0004f) ? x : r;
}

// ---------------- global state ----------------
// h ring: L2-resident, double-buffered; h(t) lives in g_ring[t&1].
__device__ float g_ring[2][BATCH][DH];
// flags: g_flag[(bg*16+cg)*32]; monotone within a replay; reset at t==SEQ-1.
__device__ unsigned g_flag[8 * 16 * 32];

// ---------------- Kernel 1: xi = x @ W_i2h^T + b_i2h (f32x2 packed) ----------------
#define BM 64
#define BN 64
#define BK 16

__global__ void __launch_bounds__(256) i2h_gemm_kernel(
    const float* __restrict__ A, const float* __restrict__ Bw,
    const float* __restrict__ bias, float* __restrict__ C)
{
    __shared__ float As[BK][BM + 4];
    __shared__ float Bs[BK][BN + 4];
    const int bm = blockIdx.x, bn = blockIdx.y, tid = threadIdx.x;
    const int tm = (tid / 16) * 4, tn = (tid % 16) * 4;
    const int lr = tid / 4, lk = (tid % 4) * 4;
    const float* Aptr = A + ((size_t)bm * BM + lr) * DIN + lk;
    const float* Bptr = Bw + ((size_t)bn * BN + lr) * DIN + lk;

    u64 acc2[4][2];
    #pragma unroll
    for (int i = 0; i < 4; i++) { acc2[i][0] = 0ull; acc2[i][1] = 0ull; }

    for (int k0 = 0; k0 < DIN; k0 += BK) {
        float4 av = *(const float4*)(Aptr + k0);
        float4 bv = *(const float4*)(Bptr + k0);
        As[lk + 0][lr] = av.x; As[lk + 1][lr] = av.y;
        As[lk + 2][lr] = av.z; As[lk + 3][lr] = av.w;
        Bs[lk + 0][lr] = bv.x; Bs[lk + 1][lr] = bv.y;
        Bs[lk + 2][lr] = bv.z; Bs[lk + 3][lr] = bv.w;
        __syncthreads();
        #pragma unroll
        for (int k = 0; k < BK; k++) {
            float4 a4 = *(const float4*)&As[k][tm];
            u64 b01 = *(const u64*)&Bs[k][tn];
            u64 b23 = *(const u64*)&Bs[k][tn + 2];
            float am[4] = {a4.x, a4.y, a4.z, a4.w};
            #pragma unroll
            for (int i = 0; i < 4; i++) {
                u64 ad = dupf(am[i]);
                fma2(acc2[i][0], ad, b01);
                fma2(acc2[i][1], ad, b23);
            }
        }
        __syncthreads();
    }

    const float b0 = bias[bn * BN + tn + 0];
    const float b1 = bias[bn * BN + tn + 1];
    const float b2 = bias[bn * BN + tn + 2];
    const float b3 = bias[bn * BN + tn + 3];
    #pragma unroll
    for (int i = 0; i < 4; i++) {
        float2 p0 = unpack2(acc2[i][0]);
        float2 p1 = unpack2(acc2[i][1]);
        float4 o;
        o.x = p0.x + b0;
        o.y = p0.y + b1;
        o.z = p1.x + b2;
        o.w = p1.y + b3;
        *(float4*)&C[((size_t)bm * BM + tm + i) * DH + bn * BN + tn] = o;
    }
}

// ---------------- Kernel 2: persistent scan (R6 loop + lean sync) ----------------
// 128 CTAs = bg(8 x 8 rows) x cg(16 x 32 cols). 128 threads = 4 warps.
// Warp w handles rows {2w, 2w+1}; lane = column. h read DIRECTLY from the L2
// ring via __ldcg (warp-uniform address -> broadcast). Per output: ONE
// ascending-k fp32 FMA chain (init 0) -> (xi+dot)+b -> xla_tanh.
#define WSTRIDE 516

__global__ void __launch_bounds__(128, 1) rnn_scan_kernel(
    const float* __restrict__ h0, const float* __restrict__ W_h2h,
    const float* __restrict__ b_h2h, float* __restrict__ out,
    float* __restrict__ h_last)
{
    extern __shared__ float W_s[];        // [32][WSTRIDE]

    const int cg = blockIdx.x & 15;
    const int bg = blockIdx.x >> 4;
    const int c0 = cg * 32;
    const int b0 = bg * 8;
    const int tid = threadIdx.x;
    const int lane = tid & 31;
    const int w = tid >> 5;
    const int rA = 2 * w, rB = 2 * w + 1;
    const int col = c0 + lane;

    // stage W slice once: W_s[c][k] = W_h2h[(c0+c)*DH + k]
    for (int idx = tid; idx < 32 * 512; idx += 128) {
        int c = idx >> 9, k = idx & 511;
        W_s[c * WSTRIDE + k] = W_h2h[(size_t)(c0 + c) * DH + k];
    }
    const float bias = b_h2h[col];
    const float4* Wp = (const float4*)&W_s[lane * WSTRIDE];

    const size_t oA = ((size_t)b0 + rA) * DH + col;   // + t*BATCH*DH
    const size_t oB = ((size_t)b0 + rB) * DH + col;
    unsigned* myflag = &g_flag[(bg * 16 + cg) * 32];
    unsigned* grpflag = &g_flag[(bg * 16 + (tid & 15)) * 32];

    // prefetch xi(0)
    float xiA = out[oA];
    float xiB = out[oB];
    __syncthreads();

    for (int t = 0; t < SEQ; t++) {
        // h(t-1) source: h0 at t=0, else ring parity of t-1
        const float4* hA4 = (t == 0)
            ? (const float4*)(h0 + (size_t)(b0 + rA) * DH)
            : (const float4*)(g_ring[1 ^ (t & 1)][b0 + rA]);
        const float4* hB4 = (t == 0)
            ? (const float4*)(h0 + (size_t)(b0 + rB) * DH)
            : (const float4*)(g_ring[1 ^ (t & 1)][b0 + rB]);

        // two ascending-k scalar chains; h via L2 (__ldcg), warp-broadcast
        float a0 = 0.f, a1 = 0.f;
        #pragma unroll 8
        for (int k4 = 0; k4 < 128; k4++) {
            float4 wv = Wp[k4];
            float4 ha = __ldcg(hA4 + k4);
            float4 hb = __ldcg(hB4 + k4);
            a0 = __fmaf_rn(ha.x, wv.x, a0);
            a0 = __fmaf_rn(ha.y, wv.y, a0);
            a0 = __fmaf_rn(ha.z, wv.z, a0);
            a0 = __fmaf_rn(ha.w, wv.w, a0);
            a1 = __fmaf_rn(hb.x, wv.x, a1);
            a1 = __fmaf_rn(hb.y, wv.y, a1);
            a1 = __fmaf_rn(hb.z, wv.z, a1);
            a1 = __fmaf_rn(hb.w, wv.w, a1);
        }

        float vA = xla_tanh((xiA + a0) + bias);
        float vB = xla_tanh((xiB + a1) + bias);

        // fire-and-forget output
        out[(size_t)t * BATCH * DH + oA] = vA;
        out[(size_t)t * BATCH * DH + oB] = vB;

        if (t == SEQ - 1) {
            if (h_last) { h_last[oA] = vA; h_last[oB] = vB; }
            __syncthreads();
            if (tid == 0) *myflag = 0u;      // replay-clean (launch boundary fences)
        } else {
            // h(t) into the hot ring
            g_ring[t & 1][b0 + rA][col] = vA;
            g_ring[t & 1][b0 + rB][col] = vB;
            // prefetch xi(t+1); overlaps the flag spin
            xiA = out[(size_t)(t + 1) * BATCH * DH + oA];
            xiB = out[(size_t)(t + 1) * BATCH * DH + oB];
            __syncthreads();                 // CTA stores done (cumulativity)
            if (tid == 0) st_release_gpu(myflag, (unsigned)(t + 1));
            if (tid < 16) {
                while (ld_acquire_gpu(grpflag) < (unsigned)(t + 1)) { }
            }
            __syncthreads();                 // acquire covers CTA (cumulativity)
        }
    }
}

// ---------------- launch (single stream, graph-capture-safe) ----------------
extern "C" void kernel_launch(void* const* d_in, const int* in_sizes, int n_in,
                              void* d_out, int out_size) {
    const float* x     = (const float*)d_in[0];
    const float* h0    = (const float*)d_in[1];
    const float* W_i2h = (const float*)d_in[2];
    const float* b_i2h = (const float*)d_in[3];
    const float* W_h2h = (const float*)d_in[4];
    const float* b_h2h = (const float*)d_in[5];
    float* out = (float*)d_out;

    float* h_last = nullptr;
    if ((long long)out_size >= (long long)(SEQ + 1) * BATCH * DH)
        h_last = out + (size_t)SEQ * BATCH * DH;

    dim3 g1(SEQ * BATCH / BM, DH / BN);
    i2h_gemm_kernel<<<g1, 256>>>(x, W_i2h, b_i2h, out);

    const int smem = 32 * WSTRIDE * sizeof(float);
    cudaFuncSetAttribute(rnn_scan_kernel,
                         cudaFuncAttributeMaxDynamicSharedMemorySize, smem);
    rnn_scan_kernel<<<128, 128, smem>>>(h0, W_h2h, b_h2h, out, h_last);
}

// round 13
// speedup vs baseline: 1.6274x; 1.4990x over previous
#include <cuda_runtime.h>
#include <math.h>

#define SEQ   2048
#define BATCH 64
#define DIN   512
#define DH    512

typedef unsigned long long u64;

// ---------------- f32x2 packed helpers (GEMM only) ----------------
__device__ __forceinline__ u64 dupf(float x) {
    u64 d; asm("mov.b64 %0, {%1, %1};" : "=l"(d) : "f"(x)); return d;
}
__device__ __forceinline__ void fma2(u64& acc, u64 a, u64 b) {
    asm("fma.rn.f32x2 %0, %1, %2, %0;" : "+l"(acc) : "l"(a), "l"(b));
}
__device__ __forceinline__ float2 unpack2(u64 v) {
    float lo, hi;
    asm("mov.b64 {%0, %1}, %2;" : "=f"(lo), "=f"(hi) : "l"(v));
    return make_float2(lo, hi);
}

// ---------------- release/acquire flag ops ----------------
__device__ __forceinline__ void st_release_gpu(unsigned* p, unsigned v) {
    asm volatile("st.global.release.gpu.u32 [%0], %1;" :: "l"(p), "r"(v) : "memory");
}
__device__ __forceinline__ unsigned ld_acquire_gpu(const unsigned* p) {
    unsigned v;
    asm volatile("ld.global.acquire.gpu.u32 %0, [%1];" : "=r"(v) : "l"(p) : "memory");
    return v;
}

// ---------------- XLA fast tanh: clamp 7.99881172180175781, passthrough ----------------
__device__ __forceinline__ float xla_tanh(float x) {
    const float kClamp = 7.99881172180175781f;
    float ax = fabsf(x);
    float xc = fminf(fmaxf(x, -kClamp), kClamp);
    float x2 = xc * xc;
    float p = __fmaf_rn(x2, -2.76076847742355e-16f, 2.00018790482477e-13f);
    p = __fmaf_rn(x2, p, -8.60467152213735e-11f);
    p = __fmaf_rn(x2, p, 5.12229709037114e-08f);
    p = __fmaf_rn(x2, p, 1.48572235717979e-05f);
    p = __fmaf_rn(x2, p, 6.37261928875436e-04f);
    p = __fmaf_rn(x2, p, 4.89352455891786e-03f);
    p = xc * p;
    float q = __fmaf_rn(x2, 1.19825839466702e-06f, 1.18534705686654e-04f);
    q = __fmaf_rn(x2, q, 2.26843463243900e-03f);
    q = __fmaf_rn(x2, q, 4.89352518554385e-03f);
    float r = __fdiv_rn(p, q);
    return (ax < 0.0004f) ? x : r;
}

// ---------------- global state ----------------
// h ring: L2-resident, double-buffered; h(t) lives in g_ring[t&1].
__device__ float g_ring[2][BATCH][DH];
// flags: g_flag[(bg*16+cg)*32]; monotone within a replay; reset at t==SEQ-1.
__device__ unsigned g_flag[8 * 16 * 32];

// ---------------- Kernel 1: xi = x @ W_i2h^T + b_i2h (f32x2 packed) ----------------
#define BM 64
#define BN 64
#define BK 16

__global__ void __launch_bounds__(256) i2h_gemm_kernel(
    const float* __restrict__ A, const float* __restrict__ Bw,
    const float* __restrict__ bias, float* __restrict__ C)
{
    __shared__ float As[BK][BM + 4];
    __shared__ float Bs[BK][BN + 4];
    const int bm = blockIdx.x, bn = blockIdx.y, tid = threadIdx.x;
    const int tm = (tid / 16) * 4, tn = (tid % 16) * 4;
    const int lr = tid / 4, lk = (tid % 4) * 4;
    const float* Aptr = A + ((size_t)bm * BM + lr) * DIN + lk;
    const float* Bptr = Bw + ((size_t)bn * BN + lr) * DIN + lk;

    u64 acc2[4][2];
    #pragma unroll
    for (int i = 0; i < 4; i++) { acc2[i][0] = 0ull; acc2[i][1] = 0ull; }

    for (int k0 = 0; k0 < DIN; k0 += BK) {
        float4 av = *(const float4*)(Aptr + k0);
        float4 bv = *(const float4*)(Bptr + k0);
        As[lk + 0][lr] = av.x; As[lk + 1][lr] = av.y;
        As[lk + 2][lr] = av.z; As[lk + 3][lr] = av.w;
        Bs[lk + 0][lr] = bv.x; Bs[lk + 1][lr] = bv.y;
        Bs[lk + 2][lr] = bv.z; Bs[lk + 3][lr] = bv.w;
        __syncthreads();
        #pragma unroll
        for (int k = 0; k < BK; k++) {
            float4 a4 = *(const float4*)&As[k][tm];
            u64 b01 = *(const u64*)&Bs[k][tn];
            u64 b23 = *(const u64*)&Bs[k][tn + 2];
            float am[4] = {a4.x, a4.y, a4.z, a4.w};
            #pragma unroll
            for (int i = 0; i < 4; i++) {
                u64 ad = dupf(am[i]);
                fma2(acc2[i][0], ad, b01);
                fma2(acc2[i][1], ad, b23);
            }
        }
        __syncthreads();
    }

    const float b0 = bias[bn * BN + tn + 0];
    const float b1 = bias[bn * BN + tn + 1];
    const float b2 = bias[bn * BN + tn + 2];
    const float b3 = bias[bn * BN + tn + 3];
    #pragma unroll
    for (int i = 0; i < 4; i++) {
        float2 p0 = unpack2(acc2[i][0]);
        float2 p1 = unpack2(acc2[i][1]);
        float4 o;
        o.x = p0.x + b0;
        o.y = p0.y + b1;
        o.z = p1.x + b2;
        o.w = p1.y + b3;
        *(float4*)&C[((size_t)bm * BM + tm + i) * DH + bn * BN + tn] = o;
    }
}

// ---------------- Kernel 2: persistent scan (R6 loop, lean overhead) ----------------
// 128 CTAs = bg(8 x 8 rows) x cg(16 x 32 cols). 128 threads = 4 warps.
// Warp w handles rows {2w, 2w+1}; lane = column. Each warp stages ONLY its own
// two h rows (no CTA bar before the chain). Per output: ONE ascending-k fp32
// FMA chain (init 0) -> (xi+dot)+b -> xla_tanh.
#define WST 516
#define HST 520

__global__ void __launch_bounds__(128, 1) rnn_scan_kernel(
    const float* __restrict__ h0, const float* __restrict__ W_h2h,
    const float* __restrict__ b_h2h, float* __restrict__ out,
    float* __restrict__ h_last)
{
    extern __shared__ float sm[];
    float* W_s = sm;                 // [32][WST]
    float* h_s = sm + 32 * WST;      // [8][HST]

    const int cg = blockIdx.x & 15;
    const int bg = blockIdx.x >> 4;
    const int c0 = cg * 32;
    const int b0 = bg * 8;
    const int tid = threadIdx.x;
    const int lane = tid & 31;
    const int w = tid >> 5;
    const int rA = 2 * w, rB = 2 * w + 1;
    const int col = c0 + lane;

    // stage W slice once
    for (int idx = tid; idx < 32 * 512; idx += 128) {
        int cc = idx >> 9, k = idx & 511;
        W_s[cc * WST + k] = W_h2h[(size_t)(c0 + cc) * DH + k];
    }
    const float bias = b_h2h[col];
    const float4* Wp  = (const float4*)&W_s[lane * WST];
    const float4* hA4 = (const float4*)&h_s[rA * HST];
    const float4* hB4 = (const float4*)&h_s[rB * HST];
    float4* dA = (float4*)&h_s[rA * HST];
    float4* dB = (float4*)&h_s[rB * HST];

    const size_t oA = ((size_t)b0 + rA) * DH + col;   // + t*BATCH*DH
    const size_t oB = ((size_t)b0 + rB) * DH + col;
    unsigned* myflag  = &g_flag[(bg * 16 + cg) * 32];
    unsigned* grpflag = &g_flag[(bg * 16 + (tid & 15)) * 32];

    // prefetch xi(0)
    float xiA = out[oA];
    float xiB = out[oB];
    __syncthreads();

    for (int t = 0; t < SEQ; t++) {
        // ---- per-warp staging of h(t-1) rows rA, rB ----
        if (t == 0) {
            const float4* sA = (const float4*)(h0 + (size_t)(b0 + rA) * DH);
            const float4* sB = (const float4*)(h0 + (size_t)(b0 + rB) * DH);
            #pragma unroll
            for (int j = 0; j < 4; j++) {
                dA[lane + 32 * j] = sA[lane + 32 * j];
                dB[lane + 32 * j] = sB[lane + 32 * j];
            }
        } else {
            const float4* sA = (const float4*)(g_ring[1 ^ (t & 1)][b0 + rA]);
            const float4* sB = (const float4*)(g_ring[1 ^ (t & 1)][b0 + rB]);
            #pragma unroll
            for (int j = 0; j < 4; j++) {
                dA[lane + 32 * j] = __ldcg(sA + lane + 32 * j);
                dB[lane + 32 * j] = __ldcg(sB + lane + 32 * j);
            }
        }
        __syncwarp();

        // ---- two ascending-k scalar chains (R6 loop, byte-identical math) ----
        float a0 = 0.f, a1 = 0.f;
        #pragma unroll 8
        for (int k4 = 0; k4 < 128; k4++) {
            float4 wv = Wp[k4];
            float4 ha = hA4[k4];
            float4 hb = hB4[k4];
            a0 = __fmaf_rn(ha.x, wv.x, a0);
            a0 = __fmaf_rn(ha.y, wv.y, a0);
            a0 = __fmaf_rn(ha.z, wv.z, a0);
            a0 = __fmaf_rn(ha.w, wv.w, a0);
            a1 = __fmaf_rn(hb.x, wv.x, a1);
            a1 = __fmaf_rn(hb.y, wv.y, a1);
            a1 = __fmaf_rn(hb.z, wv.z, a1);
            a1 = __fmaf_rn(hb.w, wv.w, a1);
        }

        float vA = xla_tanh((xiA + a0) + bias);
        float vB = xla_tanh((xiB + a1) + bias);

        if (t == SEQ - 1) {
            out[(size_t)t * BATCH * DH + oA] = vA;
            out[(size_t)t * BATCH * DH + oB] = vB;
            if (h_last) { h_last[oA] = vA; h_last[oB] = vB; }
            __syncthreads();
            if (tid == 0) *myflag = 0u;   // replay-clean (launch boundary fences)
        } else {
            // h(t) into the hot ring FIRST (the only stores the release must order)
            g_ring[t & 1][b0 + rA][col] = vA;
            g_ring[t & 1][b0 + rB][col] = vB;
            __syncthreads();
            if (tid == 0) st_release_gpu(myflag, (unsigned)(t + 1));
            // fire-and-forget DRAM output + xi prefetch in the poll shadow
            out[(size_t)t * BATCH * DH + oA] = vA;
            out[(size_t)t * BATCH * DH + oB] = vB;
            xiA = out[(size_t)(t + 1) * BATCH * DH + oA];
            xiB = out[(size_t)(t + 1) * BATCH * DH + oB];
            if (tid < 16) {
                while (ld_acquire_gpu(grpflag) < (unsigned)(t + 1)) { }
            }
            __syncthreads();
        }
    }
}

// ---------------- launch (single stream, graph-capture-safe) ----------------
extern "C" void kernel_launch(void* const* d_in, const int* in_sizes, int n_in,
                              void* d_out, int out_size) {
    const float* x     = (const float*)d_in[0];
    const float* h0    = (const float*)d_in[1];
    const float* W_i2h = (const float*)d_in[2];
    const float* b_i2h = (const float*)d_in[3];
    const float* W_h2h = (const float*)d_in[4];
    const float* b_h2h = (const float*)d_in[5];
    float* out = (float*)d_out;

    float* h_last = nullptr;
    if ((long long)out_size >= (long long)(SEQ + 1) * BATCH * DH)
        h_last = out + (size_t)SEQ * BATCH * DH;

    dim3 g1(SEQ * BATCH / BM, DH / BN);
    i2h_gemm_kernel<<<g1, 256>>>(x, W_i2h, b_i2h, out);

    const int smem = (32 * WST + 8 * HST) * sizeof(float);
    cudaFuncSetAttribute(rnn_scan_kernel,
                         cudaFuncAttributeMaxDynamicSharedMemorySize, smem);
    rnn_scan_kernel<<<128, 128, smem>>>(h0, W_h2h, b_h2h, out, h_last);
}